// round 14
// baseline (speedup 1.0000x reference)
#include <cuda_runtime.h>
#include <cuda_bf16.h>
#include <cstdint>
#include <math.h>

#define HID   768
#define NH    12
#define HD    64
#define SEQ   4096
#define BATCH 2
#define NROWS (BATCH * SEQ)   // 8192

// ---------------------------------------------------------------------------
// Scratch
// ---------------------------------------------------------------------------
__device__ float g_q  [(size_t)NROWS * HID];
__device__ float g_k  [(size_t)NROWS * HID];
__device__ float g_v  [(size_t)NROWS * HID];
__device__ float g_ctx[(size_t)NROWS * HID];

// ---------------------------------------------------------------------------
// mma.sync + ldmatrix helpers (legacy tensor path, plain sm_103)
// ---------------------------------------------------------------------------
__device__ __forceinline__ void mma_tf32(float* c, const uint32_t* a, const uint32_t* b) {
    asm volatile(
        "mma.sync.aligned.m16n8k8.row.col.f32.tf32.tf32.f32 "
        "{%0,%1,%2,%3}, {%4,%5,%6,%7}, {%8,%9}, {%0,%1,%2,%3};"
        : "+f"(c[0]), "+f"(c[1]), "+f"(c[2]), "+f"(c[3])
        : "r"(a[0]), "r"(a[1]), "r"(a[2]), "r"(a[3]), "r"(b[0]), "r"(b[1]));
}
__device__ __forceinline__ void mma_bf16(float* c, const uint32_t* a, const uint32_t* b) {
    asm volatile(
        "mma.sync.aligned.m16n8k16.row.col.f32.bf16.bf16.f32 "
        "{%0,%1,%2,%3}, {%4,%5,%6,%7}, {%8,%9}, {%0,%1,%2,%3};"
        : "+f"(c[0]), "+f"(c[1]), "+f"(c[2]), "+f"(c[3])
        : "r"(a[0]), "r"(a[1]), "r"(a[2]), "r"(a[3]), "r"(b[0]), "r"(b[1]));
}
__device__ __forceinline__ uint32_t fbits(float f) { return __float_as_uint(f); }
// pack (lo=p0, hi=p1) as bf16x2
__device__ __forceinline__ uint32_t bfpack(float p0, float p1) {
    uint32_t r;
    asm("cvt.rn.bf16x2.f32 %0, %1, %2;" : "=r"(r) : "f"(p1), "f"(p0));
    return r;
}
__device__ __forceinline__ uint32_t smem_u32(const void* p) {
    uint32_t a;
    asm("{ .reg .u64 t; cvta.to.shared.u64 t, %1; cvt.u32.u64 %0, t; }"
        : "=r"(a) : "l"(p));
    return a;
}
__device__ __forceinline__ void ldsm_x4(uint32_t* r, uint32_t addr) {
    asm volatile("ldmatrix.sync.aligned.m8n8.x4.shared.b16 {%0,%1,%2,%3}, [%4];"
        : "=r"(r[0]), "=r"(r[1]), "=r"(r[2]), "=r"(r[3]) : "r"(addr));
}
#define CP_ASYNC16(dst, src) \
    asm volatile("cp.async.cg.shared.global [%0], [%1], 16;" :: "r"(dst), "l"(src))
#define CP_COMMIT() asm volatile("cp.async.commit_group;" ::: "memory")
#define CP_WAIT0()  asm volatile("cp.async.wait_group 0;" ::: "memory")

// ===========================================================================
// Flash attention: QK^T in tf32 (raw fp32 bits, HW-truncated), PV in bf16.
// One CTA = (b, h, 128-query tile), 8 warps, m16 rows each.
// __launch_bounds__(256, 2): cap regs at 128 so 2 CTAs/SM stay resident
// (round-11 regression root cause: 136 regs -> 1 CTA/SM -> latency-bound).
// smem: Ks fp32 [64][68] | VtBf bf16 [64 d][72 key] | PsBf bf16 [128][72] | madd
// ===========================================================================
#define KSTR 68
#define RB   (KSTR * 4)       // 272B: bank pattern 4r, ldsm conflict-free
#define BSTR 144              // bf16 row stride bytes (72 elems): pattern 4r
#define KS_BYTES (64 * KSTR * 4)              // 17408
#define VT_BYTES (64 * BSTR)                  // 9216
#define PS_BYTES (128 * BSTR)                 // 18432
#define ATTN_SMEM (KS_BYTES + VT_BYTES + PS_BYTES + 256)

__global__ __launch_bounds__(256, 2)
void attn_mma(const float* __restrict__ Q, const float* __restrict__ K,
              const float* __restrict__ V, const float* __restrict__ mask,
              float* __restrict__ O)
{
    extern __shared__ char smc[];
    float* Ks   = (float*)smc;
    char*  VtBf = smc + KS_BYTES;
    char*  PsBf = smc + KS_BYTES + VT_BYTES;
    float* madd = (float*)(smc + KS_BYTES + VT_BYTES + PS_BYTES);

    const int tid  = threadIdx.x;
    const int wid  = tid >> 5;
    const int lane = tid & 31;
    const int grp  = lane >> 2;
    const int four = lane & 3;
    const int m0   = wid * 16;
    const int lx7  = lane & 7;

    const uint32_t KsB = smem_u32(Ks), VtB = smem_u32(VtBf), PsB = smem_u32(PsBf);
    // tf32 B pattern on Ks (stride 272B)
    const uint32_t boffK = (uint32_t)(lx7 + ((lane & 16) >> 1)) * RB
                         + ((lane & 8) ? 16u : 0u);
    // bf16 A pattern on PsBf (stride 144B)
    const uint32_t aoffP = (uint32_t)(lx7 + ((lane & 8) ? 8 : 0)) * BSTR
                         + ((lane & 16) ? 16u : 0u);
    // bf16 B pattern on VtBf
    const uint32_t boffV = (uint32_t)(lx7 + ((lane & 16) >> 1)) * BSTR
                         + ((lane & 8) ? 16u : 0u);

    const int qt = blockIdx.x, h = blockIdx.y, b = blockIdx.z;
    const int q0 = qt * 128;
    const size_t base = (size_t)b * SEQ * HID + (size_t)h * HD;

    // ---- Q fragments straight from global (raw fp32 -> tf32 by truncation) ----
    uint32_t Qa[8][4];
    {
        const float* q0p = Q + base + (size_t)(q0 + m0 + grp) * HID;
        const float* q1p = q0p + (size_t)8 * HID;
        #pragma unroll
        for (int ks = 0; ks < 8; ks++) {
            int c = ks * 8 + four;
            Qa[ks][0] = fbits(q0p[c]);
            Qa[ks][1] = fbits(q1p[c]);
            Qa[ks][2] = fbits(q0p[c + 4]);
            Qa[ks][3] = fbits(q1p[c + 4]);
        }
    }

    float ctx[8][4];
    #pragma unroll
    for (int j = 0; j < 8; j++)
        #pragma unroll
        for (int i = 0; i < 4; i++) ctx[j][i] = 0.f;
    float rs0 = 0.f, rs1 = 0.f;

    const int vd = tid & 63;            // V gather: d row
    const int vk = (tid >> 6) * 4;      // base key group

    for (int t = 0; t < SEQ / 64; t++) {
        const int k0 = t * 64;
        // ---- K chunk via cp.async (raw fp32) ----
        #pragma unroll
        for (int i = 0; i < 4; i++) {
            int s = tid + i * 256, r = s >> 4, c4 = s & 15;
            CP_ASYNC16(KsB + (uint32_t)(r * KSTR + c4 * 4) * 4,
                       &K[base + (size_t)(k0 + r) * HID + c4 * 4]);
        }
        CP_COMMIT();
        // ---- V chunk transposed -> bf16 Vt[d][key] ----
        #pragma unroll
        for (int i = 0; i < 4; i++) {
            int key = k0 + vk + i * 16;
            const float* vp = &V[base + (size_t)key * HID + vd];
            float w0 = vp[0], w1 = vp[HID], w2 = vp[2 * HID], w3 = vp[3 * HID];
            uint2 pk = make_uint2(bfpack(w0, w1), bfpack(w2, w3));
            *(uint2*)(VtBf + vd * BSTR + (vk + i * 16) * 2) = pk;
        }
        if (tid < 64)
            madd[tid] = (1.0f - mask[(size_t)b * SEQ + k0 + tid]) * -10000.0f;
        CP_WAIT0();
        __syncthreads();

        // ---- S = Q K^T (tf32); exp; stage P as bf16 ----
        #pragma unroll
        for (int p = 0; p < 4; p++) {
            float c0[4] = {0.f, 0.f, 0.f, 0.f};
            float c1[4] = {0.f, 0.f, 0.f, 0.f};
            const uint32_t kb = KsB + (uint32_t)p * (16 * RB) + boffK;
            #pragma unroll
            for (int ks = 0; ks < 8; ks++) {
                uint32_t kf[4];
                ldsm_x4(kf, kb + ks * 32);
                mma_tf32(c0, Qa[ks], kf);
                mma_tf32(c1, Qa[ks], kf + 2);
            }
            const int r = m0 + grp;
            #pragma unroll
            for (int half = 0; half < 2; half++) {
                float* c = half ? c1 : c0;
                int colb = (2 * p + half) * 8 + 2 * four;
                float ma = madd[colb], mb = madd[colb + 1];
                float p0 = __expf(c[0] * 0.125f + ma);
                float p1 = __expf(c[1] * 0.125f + mb);
                float p2 = __expf(c[2] * 0.125f + ma);
                float p3 = __expf(c[3] * 0.125f + mb);
                rs0 += p0 + p1;
                rs1 += p2 + p3;
                *(uint32_t*)(PsBf + r * BSTR + colb * 2)       = bfpack(p0, p1);
                *(uint32_t*)(PsBf + (r + 8) * BSTR + colb * 2) = bfpack(p2, p3);
            }
        }
        __syncwarp();   // P rows are warp-private

        // ---- ctx += P V  (bf16 m16n8k16) ----
        const uint32_t pb = PsB + (uint32_t)m0 * BSTR + aoffP;
        #pragma unroll
        for (int kk4 = 0; kk4 < 4; kk4++) {       // 16 keys each
            uint32_t a[4];
            ldsm_x4(a, pb + kk4 * 32);
            const uint32_t vb = VtB + kk4 * 32 + boffV;
            #pragma unroll
            for (int jdp = 0; jdp < 4; jdp++) {   // 16 d each
                uint32_t vf[4];
                ldsm_x4(vf, vb + jdp * (16 * BSTR));
                mma_bf16(ctx[2 * jdp],     a, vf);
                mma_bf16(ctx[2 * jdp + 1], a, vf + 2);
            }
        }
        __syncthreads();   // all warps done with Ks/Vt before reload
    }

    // ---- normalize and write ----
    rs0 += __shfl_xor_sync(0xffffffffu, rs0, 1);
    rs0 += __shfl_xor_sync(0xffffffffu, rs0, 2);
    rs1 += __shfl_xor_sync(0xffffffffu, rs1, 1);
    rs1 += __shfl_xor_sync(0xffffffffu, rs1, 2);
    const float inv0 = 1.0f / rs0, inv1 = 1.0f / rs1;

    const int r0 = q0 + m0 + grp, r1 = r0 + 8;
    #pragma unroll
    for (int jd = 0; jd < 8; jd++) {
        int col = jd * 8 + 2 * four;
        *(float2*)&O[base + (size_t)r0 * HID + col] =
            make_float2(ctx[jd][0] * inv0, ctx[jd][1] * inv0);
        *(float2*)&O[base + (size_t)r1 * HID + col] =
            make_float2(ctx[jd][2] * inv1, ctx[jd][3] * inv1);
    }
}

// ===========================================================================
// tf32 mma.sync projection GEMM (raw fp32 bits, no explicit cvt).
// CTA 128x128, k-chunk 32; 8 warps (2m x 4n), warp tile 64x32.
// ===========================================================================
#define GSTR 36
#define GRB  (GSTR * 4)   // 144

template <bool ADD_RESID>
__global__ __launch_bounds__(256)
void gemm_mma(const float* __restrict__ A, const float* __restrict__ W,
              const float* __restrict__ bias, const float* __restrict__ resid,
              float* __restrict__ C)
{
    __shared__ float As[128 * GSTR];   // [row][k]
    __shared__ float Ws[128 * GSTR];   // [n][k]  (W transposed)

    const int tid = threadIdx.x, wid = tid >> 5, lane = tid & 31;
    const int grp = lane >> 2, four = lane & 3;
    const int wm = wid & 1, wn = wid >> 1;
    const int m0 = wm * 64, n0 = wn * 32;
    const int bm = blockIdx.y * 128, bn = blockIdx.x * 128;
    const int lx7 = lane & 7;

    const uint32_t AsB = smem_u32(As), WsB = smem_u32(Ws);
    const uint32_t aoff = (uint32_t)(lx7 + ((lane & 8) ? 8 : 0)) * GRB
                        + ((lane & 16) ? 16u : 0u);
    const uint32_t boff = (uint32_t)(lx7 + ((lane & 16) >> 1)) * GRB
                        + ((lane & 8) ? 16u : 0u);

    float acc[4][4][4];
    #pragma unroll
    for (int mt = 0; mt < 4; mt++)
        #pragma unroll
        for (int nt = 0; nt < 4; nt++)
            #pragma unroll
            for (int i = 0; i < 4; i++) acc[mt][nt][i] = 0.f;

    for (int kc = 0; kc < HID / 32; kc++) {
        const int k0 = kc * 32;
        // stage A [128][32] via cp.async (raw fp32)
        #pragma unroll
        for (int i = 0; i < 4; i++) {
            int s = tid + i * 256, r = s >> 3, c4 = s & 7;
            CP_ASYNC16(AsB + (uint32_t)(r * GSTR + c4 * 4) * 4,
                       &A[(size_t)(bm + r) * HID + k0 + c4 * 4]);
        }
        CP_COMMIT();
        // stage W transposed -> Ws[n][k]
        #pragma unroll
        for (int i = 0; i < 4; i++) {
            int k4 = (tid >> 7) + i * 2;     // 0..7
            int n  = tid & 127;
            const float* wp = &W[(size_t)(k0 + k4 * 4) * HID + bn + n];
            float4 v;
            v.x = wp[0]; v.y = wp[HID]; v.z = wp[2 * HID]; v.w = wp[3 * HID];
            *(float4*)&Ws[n * GSTR + k4 * 4] = v;
        }
        CP_WAIT0();
        __syncthreads();

        #pragma unroll
        for (int ks = 0; ks < 4; ks++) {
            uint32_t af[4][4], bf[2][4];
            #pragma unroll
            for (int mt = 0; mt < 4; mt++)
                ldsm_x4(af[mt], AsB + (uint32_t)(m0 + mt * 16) * GRB + ks * 32 + aoff);
            #pragma unroll
            for (int np = 0; np < 2; np++)
                ldsm_x4(bf[np], WsB + (uint32_t)(n0 + np * 16) * GRB + ks * 32 + boff);
            #pragma unroll
            for (int mt = 0; mt < 4; mt++)
                #pragma unroll
                for (int nt = 0; nt < 4; nt++)
                    mma_tf32(acc[mt][nt], af[mt], &bf[nt >> 1][(nt & 1) * 2]);
        }
        __syncthreads();
    }

    // epilogue
    #pragma unroll
    for (int mt = 0; mt < 4; mt++) {
        int r0 = bm + m0 + mt * 16 + grp, r1 = r0 + 8;
        #pragma unroll
        for (int nt = 0; nt < 4; nt++) {
            int col = bn + n0 + nt * 8 + 2 * four;
            float b0 = bias[col], b1 = bias[col + 1];
            float2 o0 = make_float2(acc[mt][nt][0] + b0, acc[mt][nt][1] + b1);
            float2 o1 = make_float2(acc[mt][nt][2] + b0, acc[mt][nt][3] + b1);
            if (ADD_RESID) {
                float2 h0 = *(const float2*)&resid[(size_t)r0 * HID + col];
                float2 h1 = *(const float2*)&resid[(size_t)r1 * HID + col];
                o0.x += h0.x; o0.y += h0.y; o1.x += h1.x; o1.y += h1.y;
            }
            *(float2*)&C[(size_t)r0 * HID + col] = o0;
            *(float2*)&C[(size_t)r1 * HID + col] = o1;
        }
    }
}

// ---------------------------------------------------------------------------
// LayerNorm
// ---------------------------------------------------------------------------
__global__ __launch_bounds__(256)
void ln_kernel(float* __restrict__ X, const float* __restrict__ gamma,
               const float* __restrict__ beta)
{
    __shared__ float ss[8], ss2[8];
    const int row = blockIdx.x;
    float* x = X + (size_t)row * HID;
    const int tid = threadIdx.x;

    float v[3], s = 0.f, s2 = 0.f;
    #pragma unroll
    for (int i = 0; i < 3; i++) {
        v[i] = x[tid + i * 256];
        s += v[i]; s2 += v[i] * v[i];
    }
    #pragma unroll
    for (int off = 16; off; off >>= 1) {
        s  += __shfl_xor_sync(0xffffffffu, s,  off);
        s2 += __shfl_xor_sync(0xffffffffu, s2, off);
    }
    if ((tid & 31) == 0) { ss[tid >> 5] = s; ss2[tid >> 5] = s2; }
    __syncthreads();
    s = 0.f; s2 = 0.f;
    #pragma unroll
    for (int i = 0; i < 8; i++) { s += ss[i]; s2 += ss2[i]; }

    const float mu  = s * (1.0f / HID);
    const float var = s2 * (1.0f / HID) - mu * mu;
    const float inv = rsqrtf(var + 1e-5f);
    #pragma unroll
    for (int i = 0; i < 3; i++) {
        int c = tid + i * 256;
        x[c] = (v[i] - mu) * inv * gamma[c] + beta[c];
    }
}

// ---------------------------------------------------------------------------
// Launch
// ---------------------------------------------------------------------------
extern "C" void kernel_launch(void* const* d_in, const int* in_sizes, int n_in,
                              void* d_out, int out_size)
{
    (void)in_sizes; (void)n_in; (void)out_size;
    const float* hidden = (const float*)d_in[0];
    const float* mask   = (const float*)d_in[1];
    const float* Wq = (const float*)d_in[2];
    const float* bq = (const float*)d_in[3];
    const float* Wk = (const float*)d_in[4];
    const float* bk = (const float*)d_in[5];
    const float* Wv = (const float*)d_in[6];
    const float* bv = (const float*)d_in[7];
    const float* Wo = (const float*)d_in[8];
    const float* bo = (const float*)d_in[9];
    const float* gamma = (const float*)d_in[10];
    const float* beta  = (const float*)d_in[11];
    float* out = (float*)d_out;

    float *q, *k, *v, *ctx;
    cudaGetSymbolAddress((void**)&q,   g_q);
    cudaGetSymbolAddress((void**)&k,   g_k);
    cudaGetSymbolAddress((void**)&v,   g_v);
    cudaGetSymbolAddress((void**)&ctx, g_ctx);

    const dim3 gg(HID / 128, NROWS / 128);   // (6, 64)

    gemm_mma<false><<<gg, 256>>>(hidden, Wq, bq, nullptr, q);
    gemm_mma<false><<<gg, 256>>>(hidden, Wk, bk, nullptr, k);
    gemm_mma<false><<<gg, 256>>>(hidden, Wv, bv, nullptr, v);

    cudaFuncSetAttribute(attn_mma, cudaFuncAttributeMaxDynamicSharedMemorySize,
                         ATTN_SMEM);
    attn_mma<<<dim3(SEQ / 128, NH, BATCH), 256, ATTN_SMEM>>>(q, k, v, mask, ctx);

    gemm_mma<true><<<gg, 256>>>(ctx, Wo, bo, hidden, out);
    ln_kernel<<<NROWS, 256>>>(out, gamma, beta);
}

// round 15
// speedup vs baseline: 1.6136x; 1.6136x over previous
#include <cuda_runtime.h>
#include <cuda_bf16.h>
#include <cstdint>
#include <math.h>

#define HID   768
#define NH    12
#define HD    64
#define SEQ   4096
#define BATCH 2
#define NROWS (BATCH * SEQ)   // 8192

// ---------------------------------------------------------------------------
// Scratch
// ---------------------------------------------------------------------------
__device__ float g_q  [(size_t)NROWS * HID];
__device__ float g_k  [(size_t)NROWS * HID];
__device__ float g_v  [(size_t)NROWS * HID];
__device__ float g_ctx[(size_t)NROWS * HID];

// ---------------------------------------------------------------------------
// mma.sync + ldmatrix helpers (legacy tensor path, plain sm_103)
// ---------------------------------------------------------------------------
__device__ __forceinline__ void mma_tf32(float* c, const uint32_t* a, const uint32_t* b) {
    asm volatile(
        "mma.sync.aligned.m16n8k8.row.col.f32.tf32.tf32.f32 "
        "{%0,%1,%2,%3}, {%4,%5,%6,%7}, {%8,%9}, {%0,%1,%2,%3};"
        : "+f"(c[0]), "+f"(c[1]), "+f"(c[2]), "+f"(c[3])
        : "r"(a[0]), "r"(a[1]), "r"(a[2]), "r"(a[3]), "r"(b[0]), "r"(b[1]));
}
__device__ __forceinline__ void mma_bf16(float* c, const uint32_t* a, const uint32_t* b) {
    asm volatile(
        "mma.sync.aligned.m16n8k16.row.col.f32.bf16.bf16.f32 "
        "{%0,%1,%2,%3}, {%4,%5,%6,%7}, {%8,%9}, {%0,%1,%2,%3};"
        : "+f"(c[0]), "+f"(c[1]), "+f"(c[2]), "+f"(c[3])
        : "r"(a[0]), "r"(a[1]), "r"(a[2]), "r"(a[3]), "r"(b[0]), "r"(b[1]));
}
__device__ __forceinline__ uint32_t fbits(float f) { return __float_as_uint(f); }
__device__ __forceinline__ uint32_t bfpack(float p0, float p1) {   // lo=p0, hi=p1
    uint32_t r;
    asm("cvt.rn.bf16x2.f32 %0, %1, %2;" : "=r"(r) : "f"(p1), "f"(p0));
    return r;
}
__device__ __forceinline__ uint32_t smem_u32(const void* p) {
    uint32_t a;
    asm("{ .reg .u64 t; cvta.to.shared.u64 t, %1; cvt.u32.u64 %0, t; }"
        : "=r"(a) : "l"(p));
    return a;
}
__device__ __forceinline__ void ldsm_x4(uint32_t* r, uint32_t addr) {
    asm volatile("ldmatrix.sync.aligned.m8n8.x4.shared.b16 {%0,%1,%2,%3}, [%4];"
        : "=r"(r[0]), "=r"(r[1]), "=r"(r[2]), "=r"(r[3]) : "r"(addr));
}
#define CP_ASYNC16(dst, src) \
    asm volatile("cp.async.cg.shared.global [%0], [%1], 16;" :: "r"(dst), "l"(src))
#define CP_COMMIT() asm volatile("cp.async.commit_group;" ::: "memory")
#define CP_WAIT0()  asm volatile("cp.async.wait_group 0;" ::: "memory")

// ===========================================================================
// Flash attention, fused S->P->PV in registers (the m16n8k8 C-fragment IS the
// m16n8k16 bf16 A-fragment after bfpack -> no P smem staging at all).
// Double-buffered K/V tiles via cp.async / prefetched LDG.
// One CTA = (b, h, 128-query tile), 8 warps, m16 rows each.
// smem: Ks[2] fp32 [64][68] | Vt[2] bf16 [64 d][72 key] | madd[2][64]
// ===========================================================================
#define KSTR 68
#define RB   (KSTR * 4)       // 272B row stride: bank pattern 4r, ldsm-safe
#define BSTR 144              // bf16 row stride bytes (72 elems)
#define KS_BYTES (64 * KSTR * 4)              // 17408 per stage
#define VT_BYTES (64 * BSTR)                  // 9216 per stage
#define MADD_OFF (2 * KS_BYTES + 2 * VT_BYTES)
#define ATTN_SMEM (MADD_OFF + 2 * 64 * 4 + 128)
#define NT (SEQ / 64)

__global__ __launch_bounds__(256, 2)
void attn_mma(const float* __restrict__ Q, const float* __restrict__ K,
              const float* __restrict__ V, const float* __restrict__ mask,
              float* __restrict__ O)
{
    extern __shared__ char smc[];
    float* madd = (float*)(smc + MADD_OFF);

    const int tid  = threadIdx.x;
    const int wid  = tid >> 5;
    const int lane = tid & 31;
    const int grp  = lane >> 2;
    const int four = lane & 3;
    const int m0   = wid * 16;
    const int lx7  = lane & 7;

    const uint32_t smB = smem_u32(smc);
    // tf32 B pattern on Ks (stride 272B)
    const uint32_t boffK = (uint32_t)(lx7 + ((lane & 16) >> 1)) * RB
                         + ((lane & 8) ? 16u : 0u);
    // bf16 B pattern on Vt (stride 144B)
    const uint32_t boffV = (uint32_t)(lx7 + ((lane & 16) >> 1)) * BSTR
                         + ((lane & 8) ? 16u : 0u);

    const int qt = blockIdx.x, h = blockIdx.y, b = blockIdx.z;
    const int q0 = qt * 128;
    const size_t base = (size_t)b * SEQ * HID + (size_t)h * HD;

    // ---- Q fragments straight from global (fp32 bits; HMMA truncates) ----
    uint32_t Qa[8][4];
    {
        const float* q0p = Q + base + (size_t)(q0 + m0 + grp) * HID;
        const float* q1p = q0p + (size_t)8 * HID;
        #pragma unroll
        for (int ks = 0; ks < 8; ks++) {
            int c = ks * 8 + four;
            Qa[ks][0] = fbits(q0p[c]);
            Qa[ks][1] = fbits(q1p[c]);
            Qa[ks][2] = fbits(q0p[c + 4]);
            Qa[ks][3] = fbits(q1p[c + 4]);
        }
    }

    float ctx[8][4];
    #pragma unroll
    for (int j = 0; j < 8; j++)
        #pragma unroll
        for (int i = 0; i < 4; i++) ctx[j][i] = 0.f;
    float rs0 = 0.f, rs1 = 0.f;

    const int vd = tid & 63;            // V gather: d row
    const int vk = (tid >> 6) * 4;      // base key group

    float vr[16];                       // in-flight V prefetch
    float mreg = 0.f;

    // ---- prologue: stage tile 0 ----
    {
        #pragma unroll
        for (int i = 0; i < 4; i++) {
            int s = tid + i * 256, r = s >> 4, c4 = s & 15;
            CP_ASYNC16(smB + (uint32_t)(r * KSTR + c4 * 4) * 4,
                       &K[base + (size_t)r * HID + c4 * 4]);
        }
        CP_COMMIT();
        #pragma unroll
        for (int i = 0; i < 4; i++) {
            int key = vk + i * 16;
            const float* vp = &V[base + (size_t)key * HID + vd];
            vr[4*i+0] = vp[0]; vr[4*i+1] = vp[HID];
            vr[4*i+2] = vp[2*HID]; vr[4*i+3] = vp[3*HID];
        }
        #pragma unroll
        for (int i = 0; i < 4; i++) {
            uint2 pk = make_uint2(bfpack(vr[4*i], vr[4*i+1]),
                                  bfpack(vr[4*i+2], vr[4*i+3]));
            *(uint2*)(smc + 2*KS_BYTES + vd * BSTR + (vk + i * 16) * 2) = pk;
        }
        if (tid < 64)
            madd[tid] = (1.0f - mask[(size_t)b * SEQ + tid]) * -10000.0f;
        CP_WAIT0();
        __syncthreads();
    }

    for (int t = 0; t < NT; t++) {
        const int st  = t & 1;
        const int nst = st ^ 1;
        const bool more = (t + 1) < NT;

        // ---- issue stage t+1 (K cp.async, V LDGs into regs, mask LDG) ----
        if (more) {
            const int k1 = (t + 1) * 64;
            #pragma unroll
            for (int i = 0; i < 4; i++) {
                int s = tid + i * 256, r = s >> 4, c4 = s & 15;
                CP_ASYNC16(smB + (uint32_t)nst * KS_BYTES
                               + (uint32_t)(r * KSTR + c4 * 4) * 4,
                           &K[base + (size_t)(k1 + r) * HID + c4 * 4]);
            }
            CP_COMMIT();
            #pragma unroll
            for (int i = 0; i < 4; i++) {
                int key = k1 + vk + i * 16;
                const float* vp = &V[base + (size_t)key * HID + vd];
                vr[4*i+0] = vp[0]; vr[4*i+1] = vp[HID];
                vr[4*i+2] = vp[2*HID]; vr[4*i+3] = vp[3*HID];
            }
            if (tid < 64)
                mreg = mask[(size_t)b * SEQ + k1 + tid];
        }

        // ---- compute tile t: fused S -> exp -> PV per 16-key group ----
        const uint32_t KsBuf = smB + (uint32_t)st * KS_BYTES;
        const uint32_t VtBuf = smB + 2 * KS_BYTES + (uint32_t)st * VT_BYTES;
        const float* md = madd + st * 64;

        #pragma unroll
        for (int p = 0; p < 4; p++) {
            float c0[4] = {0.f, 0.f, 0.f, 0.f};
            float c1[4] = {0.f, 0.f, 0.f, 0.f};
            const uint32_t kb = KsBuf + (uint32_t)p * (16 * RB) + boffK;
            #pragma unroll
            for (int ks = 0; ks < 8; ks++) {
                uint32_t kf[4];
                ldsm_x4(kf, kb + ks * 32);
                mma_tf32(c0, Qa[ks], kf);
                mma_tf32(c1, Qa[ks], kf + 2);
            }
            const int colb0 = p * 16 + 2 * four;
            const int colb1 = colb0 + 8;
            const float ma0 = md[colb0], mb0 = md[colb0 + 1];
            const float ma1 = md[colb1], mb1 = md[colb1 + 1];
            float e00 = __expf(c0[0] * 0.125f + ma0);
            float e01 = __expf(c0[1] * 0.125f + mb0);
            float e02 = __expf(c0[2] * 0.125f + ma0);
            float e03 = __expf(c0[3] * 0.125f + mb0);
            float e10 = __expf(c1[0] * 0.125f + ma1);
            float e11 = __expf(c1[1] * 0.125f + mb1);
            float e12 = __expf(c1[2] * 0.125f + ma1);
            float e13 = __expf(c1[3] * 0.125f + mb1);
            rs0 += e00 + e01 + e10 + e11;
            rs1 += e02 + e03 + e12 + e13;
            // C-fragment == bf16 A-fragment after packing (no smem roundtrip)
            uint32_t a[4];
            a[0] = bfpack(e00, e01);
            a[1] = bfpack(e02, e03);
            a[2] = bfpack(e10, e11);
            a[3] = bfpack(e12, e13);

            const uint32_t vb = VtBuf + (uint32_t)p * 32 + boffV;
            #pragma unroll
            for (int jdp = 0; jdp < 4; jdp++) {
                uint32_t vf[4];
                ldsm_x4(vf, vb + jdp * (16 * BSTR));
                mma_bf16(ctx[2 * jdp],     a, vf);
                mma_bf16(ctx[2 * jdp + 1], a, vf + 2);
            }
        }

        // ---- complete stage t+1 (V/mask stores), fence ----
        if (more) {
            #pragma unroll
            for (int i = 0; i < 4; i++) {
                uint2 pk = make_uint2(bfpack(vr[4*i], vr[4*i+1]),
                                      bfpack(vr[4*i+2], vr[4*i+3]));
                *(uint2*)(smc + 2*KS_BYTES + nst * VT_BYTES
                              + vd * BSTR + (vk + i * 16) * 2) = pk;
            }
            if (tid < 64)
                madd[nst * 64 + tid] = (1.0f - mreg) * -10000.0f;
            CP_WAIT0();
            __syncthreads();
        }
    }

    // ---- normalize and write ----
    rs0 += __shfl_xor_sync(0xffffffffu, rs0, 1);
    rs0 += __shfl_xor_sync(0xffffffffu, rs0, 2);
    rs1 += __shfl_xor_sync(0xffffffffu, rs1, 1);
    rs1 += __shfl_xor_sync(0xffffffffu, rs1, 2);
    const float inv0 = 1.0f / rs0, inv1 = 1.0f / rs1;

    const int r0 = q0 + m0 + grp, r1 = r0 + 8;
    #pragma unroll
    for (int jd = 0; jd < 8; jd++) {
        int col = jd * 8 + 2 * four;
        *(float2*)&O[base + (size_t)r0 * HID + col] =
            make_float2(ctx[jd][0] * inv0, ctx[jd][1] * inv0);
        *(float2*)&O[base + (size_t)r1 * HID + col] =
            make_float2(ctx[jd][2] * inv1, ctx[jd][3] * inv1);
    }
}

// ===========================================================================
// tf32 mma.sync projection GEMM (raw fp32 bits, no explicit cvt).
// CTA 128x128, k-chunk 32; 8 warps (2m x 4n), warp tile 64x32.
// ===========================================================================
#define GSTR 36
#define GRB  (GSTR * 4)   // 144

template <bool ADD_RESID>
__global__ __launch_bounds__(256)
void gemm_mma(const float* __restrict__ A, const float* __restrict__ W,
              const float* __restrict__ bias, const float* __restrict__ resid,
              float* __restrict__ C)
{
    __shared__ float As[128 * GSTR];   // [row][k]
    __shared__ float Ws[128 * GSTR];   // [n][k]  (W transposed)

    const int tid = threadIdx.x, wid = tid >> 5, lane = tid & 31;
    const int grp = lane >> 2, four = lane & 3;
    const int wm = wid & 1, wn = wid >> 1;
    const int m0 = wm * 64, n0 = wn * 32;
    const int bm = blockIdx.y * 128, bn = blockIdx.x * 128;
    const int lx7 = lane & 7;

    const uint32_t AsB = smem_u32(As), WsB = smem_u32(Ws);
    const uint32_t aoff = (uint32_t)(lx7 + ((lane & 8) ? 8 : 0)) * GRB
                        + ((lane & 16) ? 16u : 0u);
    const uint32_t boff = (uint32_t)(lx7 + ((lane & 16) >> 1)) * GRB
                        + ((lane & 8) ? 16u : 0u);

    float acc[4][4][4];
    #pragma unroll
    for (int mt = 0; mt < 4; mt++)
        #pragma unroll
        for (int nt = 0; nt < 4; nt++)
            #pragma unroll
            for (int i = 0; i < 4; i++) acc[mt][nt][i] = 0.f;

    for (int kc = 0; kc < HID / 32; kc++) {
        const int k0 = kc * 32;
        #pragma unroll
        for (int i = 0; i < 4; i++) {
            int s = tid + i * 256, r = s >> 3, c4 = s & 7;
            CP_ASYNC16(AsB + (uint32_t)(r * GSTR + c4 * 4) * 4,
                       &A[(size_t)(bm + r) * HID + k0 + c4 * 4]);
        }
        CP_COMMIT();
        #pragma unroll
        for (int i = 0; i < 4; i++) {
            int k4 = (tid >> 7) + i * 2;     // 0..7
            int n  = tid & 127;
            const float* wp = &W[(size_t)(k0 + k4 * 4) * HID + bn + n];
            float4 v;
            v.x = wp[0]; v.y = wp[HID]; v.z = wp[2 * HID]; v.w = wp[3 * HID];
            *(float4*)&Ws[n * GSTR + k4 * 4] = v;
        }
        CP_WAIT0();
        __syncthreads();

        #pragma unroll
        for (int ks = 0; ks < 4; ks++) {
            uint32_t af[4][4], bf[2][4];
            #pragma unroll
            for (int mt = 0; mt < 4; mt++)
                ldsm_x4(af[mt], AsB + (uint32_t)(m0 + mt * 16) * GRB + ks * 32 + aoff);
            #pragma unroll
            for (int np = 0; np < 2; np++)
                ldsm_x4(bf[np], WsB + (uint32_t)(n0 + np * 16) * GRB + ks * 32 + boff);
            #pragma unroll
            for (int mt = 0; mt < 4; mt++)
                #pragma unroll
                for (int nt = 0; nt < 4; nt++)
                    mma_tf32(acc[mt][nt], af[mt], &bf[nt >> 1][(nt & 1) * 2]);
        }
        __syncthreads();
    }

    #pragma unroll
    for (int mt = 0; mt < 4; mt++) {
        int r0 = bm + m0 + mt * 16 + grp, r1 = r0 + 8;
        #pragma unroll
        for (int nt = 0; nt < 4; nt++) {
            int col = bn + n0 + nt * 8 + 2 * four;
            float b0 = bias[col], b1 = bias[col + 1];
            float2 o0 = make_float2(acc[mt][nt][0] + b0, acc[mt][nt][1] + b1);
            float2 o1 = make_float2(acc[mt][nt][2] + b0, acc[mt][nt][3] + b1);
            if (ADD_RESID) {
                float2 h0 = *(const float2*)&resid[(size_t)r0 * HID + col];
                float2 h1 = *(const float2*)&resid[(size_t)r1 * HID + col];
                o0.x += h0.x; o0.y += h0.y; o1.x += h1.x; o1.y += h1.y;
            }
            *(float2*)&C[(size_t)r0 * HID + col] = o0;
            *(float2*)&C[(size_t)r1 * HID + col] = o1;
        }
    }
}

// ---------------------------------------------------------------------------
// LayerNorm
// ---------------------------------------------------------------------------
__global__ __launch_bounds__(256)
void ln_kernel(float* __restrict__ X, const float* __restrict__ gamma,
               const float* __restrict__ beta)
{
    __shared__ float ss[8], ss2[8];
    const int row = blockIdx.x;
    float* x = X + (size_t)row * HID;
    const int tid = threadIdx.x;

    float v[3], s = 0.f, s2 = 0.f;
    #pragma unroll
    for (int i = 0; i < 3; i++) {
        v[i] = x[tid + i * 256];
        s += v[i]; s2 += v[i] * v[i];
    }
    #pragma unroll
    for (int off = 16; off; off >>= 1) {
        s  += __shfl_xor_sync(0xffffffffu, s,  off);
        s2 += __shfl_xor_sync(0xffffffffu, s2, off);
    }
    if ((tid & 31) == 0) { ss[tid >> 5] = s; ss2[tid >> 5] = s2; }
    __syncthreads();
    s = 0.f; s2 = 0.f;
    #pragma unroll
    for (int i = 0; i < 8; i++) { s += ss[i]; s2 += ss2[i]; }

    const float mu  = s * (1.0f / HID);
    const float var = s2 * (1.0f / HID) - mu * mu;
    const float inv = rsqrtf(var + 1e-5f);
    #pragma unroll
    for (int i = 0; i < 3; i++) {
        int c = tid + i * 256;
        x[c] = (v[i] - mu) * inv * gamma[c] + beta[c];
    }
}

// ---------------------------------------------------------------------------
// Launch
// ---------------------------------------------------------------------------
extern "C" void kernel_launch(void* const* d_in, const int* in_sizes, int n_in,
                              void* d_out, int out_size)
{
    (void)in_sizes; (void)n_in; (void)out_size;
    const float* hidden = (const float*)d_in[0];
    const float* mask   = (const float*)d_in[1];
    const float* Wq = (const float*)d_in[2];
    const float* bq = (const float*)d_in[3];
    const float* Wk = (const float*)d_in[4];
    const float* bk = (const float*)d_in[5];
    const float* Wv = (const float*)d_in[6];
    const float* bv = (const float*)d_in[7];
    const float* Wo = (const float*)d_in[8];
    const float* bo = (const float*)d_in[9];
    const float* gamma = (const float*)d_in[10];
    const float* beta  = (const float*)d_in[11];
    float* out = (float*)d_out;

    float *q, *k, *v, *ctx;
    cudaGetSymbolAddress((void**)&q,   g_q);
    cudaGetSymbolAddress((void**)&k,   g_k);
    cudaGetSymbolAddress((void**)&v,   g_v);
    cudaGetSymbolAddress((void**)&ctx, g_ctx);

    const dim3 gg(HID / 128, NROWS / 128);   // (6, 64)

    gemm_mma<false><<<gg, 256>>>(hidden, Wq, bq, nullptr, q);
    gemm_mma<false><<<gg, 256>>>(hidden, Wk, bk, nullptr, k);
    gemm_mma<false><<<gg, 256>>>(hidden, Wv, bv, nullptr, v);

    cudaFuncSetAttribute(attn_mma, cudaFuncAttributeMaxDynamicSharedMemorySize,
                         ATTN_SMEM);
    attn_mma<<<dim3(SEQ / 128, NH, BATCH), 256, ATTN_SMEM>>>(q, k, v, mask, ctx);

    gemm_mma<true><<<gg, 256>>>(ctx, Wo, bo, hidden, out);
    ln_kernel<<<NROWS, 256>>>(out, gamma, beta);
}

// round 17
// speedup vs baseline: 1.7677x; 1.0955x over previous
#include <cuda_runtime.h>
#include <cuda_bf16.h>
#include <cstdint>
#include <math.h>

#define HID   768
#define NH    12
#define HD    64
#define SEQ   4096
#define BATCH 2
#define NROWS (BATCH * SEQ)   // 8192

// ---------------------------------------------------------------------------
// Scratch
// ---------------------------------------------------------------------------
__device__ float g_q  [(size_t)NROWS * HID];
__device__ float g_k  [(size_t)NROWS * HID];
__device__ float g_v  [(size_t)NROWS * HID];
__device__ float g_ctx[(size_t)NROWS * HID];

// ---------------------------------------------------------------------------
// mma.sync + ldmatrix helpers (legacy tensor path, plain sm_103)
// ---------------------------------------------------------------------------
__device__ __forceinline__ void mma_tf32(float* c, const uint32_t* a, const uint32_t* b) {
    asm volatile(
        "mma.sync.aligned.m16n8k8.row.col.f32.tf32.tf32.f32 "
        "{%0,%1,%2,%3}, {%4,%5,%6,%7}, {%8,%9}, {%0,%1,%2,%3};"
        : "+f"(c[0]), "+f"(c[1]), "+f"(c[2]), "+f"(c[3])
        : "r"(a[0]), "r"(a[1]), "r"(a[2]), "r"(a[3]), "r"(b[0]), "r"(b[1]));
}
__device__ __forceinline__ void mma_bf16(float* c, const uint32_t* a, const uint32_t* b) {
    asm volatile(
        "mma.sync.aligned.m16n8k16.row.col.f32.bf16.bf16.f32 "
        "{%0,%1,%2,%3}, {%4,%5,%6,%7}, {%8,%9}, {%0,%1,%2,%3};"
        : "+f"(c[0]), "+f"(c[1]), "+f"(c[2]), "+f"(c[3])
        : "r"(a[0]), "r"(a[1]), "r"(a[2]), "r"(a[3]), "r"(b[0]), "r"(b[1]));
}
__device__ __forceinline__ uint32_t fbits(float f) { return __float_as_uint(f); }
__device__ __forceinline__ uint32_t bfpack(float p0, float p1) {   // lo=p0, hi=p1
    uint32_t r;
    asm("cvt.rn.bf16x2.f32 %0, %1, %2;" : "=r"(r) : "f"(p1), "f"(p0));
    return r;
}
__device__ __forceinline__ uint32_t smem_u32(const void* p) {
    uint32_t a;
    asm("{ .reg .u64 t; cvta.to.shared.u64 t, %1; cvt.u32.u64 %0, t; }"
        : "=r"(a) : "l"(p));
    return a;
}
__device__ __forceinline__ void ldsm_x4(uint32_t* r, uint32_t addr) {
    asm volatile("ldmatrix.sync.aligned.m8n8.x4.shared.b16 {%0,%1,%2,%3}, [%4];"
        : "=r"(r[0]), "=r"(r[1]), "=r"(r[2]), "=r"(r[3]) : "r"(addr));
}
#define CP_ASYNC16(dst, src) \
    asm volatile("cp.async.cg.shared.global [%0], [%1], 16;" :: "r"(dst), "l"(src))
#define CP_COMMIT() asm volatile("cp.async.commit_group;" ::: "memory")
#define CP_WAIT0()  asm volatile("cp.async.wait_group 0;" ::: "memory")

// ===========================================================================
// Flash attention, all-bf16 MMA path:
//   QK^T bf16 m16n8k16 (K stored bf16, n-major rows)  -> halves K ldsm + MMAs
//   P = exp(...) packed straight into bf16 A-fragments (no smem staging)
//   PV  bf16 m16n8k16 with transposed V
// Double-buffered K/V via register prefetch. 8 warps, m16 rows each.
// smem: Ks[2] bf16 [64 key][72 d] | Vt[2] bf16 [64 d][72 key] | madd[2][64]
// ===========================================================================
#define BSTR 144              // bf16 row stride bytes (72 elems): bank 4r
#define KS_BYTES (64 * BSTR)                  // 9216 per stage
#define VT_BYTES (64 * BSTR)                  // 9216 per stage
#define MADD_OFF (2 * KS_BYTES + 2 * VT_BYTES)
#define ATTN_SMEM (MADD_OFF + 2 * 64 * 4 + 128)
#define NT (SEQ / 64)

__global__ __launch_bounds__(256, 2)
void attn_mma(const float* __restrict__ Q, const float* __restrict__ K,
              const float* __restrict__ V, const float* __restrict__ mask,
              float* __restrict__ O)
{
    extern __shared__ char smc[];
    float* madd = (float*)(smc + MADD_OFF);

    const int tid  = threadIdx.x;
    const int wid  = tid >> 5;
    const int lane = tid & 31;
    const int grp  = lane >> 2;
    const int four = lane & 3;
    const int m0   = wid * 16;
    const int lx7  = lane & 7;

    const uint32_t smB = smem_u32(smc);
    // bf16 B-fragment ldmatrix pattern (stride BSTR), used for both Ks and Vt
    const uint32_t boffB = (uint32_t)(lx7 + ((lane & 16) >> 1)) * BSTR
                         + ((lane & 8) ? 16u : 0u);

    const int qt = blockIdx.x, h = blockIdx.y, b = blockIdx.z;
    const int q0 = qt * 128;
    const size_t base = (size_t)b * SEQ * HID + (size_t)h * HD;

    // ---- Q A-fragments (bf16, packed once from global) ----
    uint32_t Qb[4][4];
    {
        const float* q0p = Q + base + (size_t)(q0 + m0 + grp) * HID;
        const float* q1p = q0p + (size_t)8 * HID;
        #pragma unroll
        for (int k16 = 0; k16 < 4; k16++) {
            int c = k16 * 16 + 2 * four;
            Qb[k16][0] = bfpack(q0p[c],     q0p[c + 1]);
            Qb[k16][1] = bfpack(q1p[c],     q1p[c + 1]);
            Qb[k16][2] = bfpack(q0p[c + 8], q0p[c + 9]);
            Qb[k16][3] = bfpack(q1p[c + 8], q1p[c + 9]);
        }
    }

    float ctx[8][4];
    #pragma unroll
    for (int j = 0; j < 8; j++)
        #pragma unroll
        for (int i = 0; i < 4; i++) ctx[j][i] = 0.f;
    float rs0 = 0.f, rs1 = 0.f;

    // staging roles
    const int krow = tid >> 2;          // K: key row 0..63
    const int kq   = tid & 3;           // K: 16-float quarter of the row
    const int vd   = tid & 63;          // V: d row
    const int vk   = (tid >> 6) * 4;    // V: base key group

    float4 kr[4];                       // K prefetch (16 floats)
    float  vr[16];                      // V prefetch
    float  mreg = 0.f;

    // ---- prologue: stage tile 0 ----
    {
        const float* kp = &K[base + (size_t)krow * HID + kq * 16];
        #pragma unroll
        for (int i = 0; i < 4; i++) kr[i] = *(const float4*)(kp + i * 4);
        #pragma unroll
        for (int i = 0; i < 4; i++) {
            int key = vk + i * 16;
            const float* vp = &V[base + (size_t)key * HID + vd];
            vr[4*i+0] = vp[0]; vr[4*i+1] = vp[HID];
            vr[4*i+2] = vp[2*HID]; vr[4*i+3] = vp[3*HID];
        }
        // pack + store K
        #pragma unroll
        for (int i = 0; i < 2; i++) {
            uint4 pk = make_uint4(bfpack(kr[2*i].x, kr[2*i].y),
                                  bfpack(kr[2*i].z, kr[2*i].w),
                                  bfpack(kr[2*i+1].x, kr[2*i+1].y),
                                  bfpack(kr[2*i+1].z, kr[2*i+1].w));
            *(uint4*)(smc + krow * BSTR + kq * 32 + i * 16) = pk;
        }
        // pack + store V (transposed)
        #pragma unroll
        for (int i = 0; i < 4; i++) {
            uint2 pk = make_uint2(bfpack(vr[4*i], vr[4*i+1]),
                                  bfpack(vr[4*i+2], vr[4*i+3]));
            *(uint2*)(smc + 2*KS_BYTES + vd * BSTR + (vk + i * 16) * 2) = pk;
        }
        if (tid < 64)
            madd[tid] = (1.0f - mask[(size_t)b * SEQ + tid]) * -10000.0f;
        __syncthreads();
    }

    for (int t = 0; t < NT; t++) {
        const int st  = t & 1;
        const int nst = st ^ 1;
        const bool more = (t + 1) < NT;

        // ---- issue LDGs for stage t+1 (K + V into regs, mask) ----
        if (more) {
            const int k1 = (t + 1) * 64;
            const float* kp = &K[base + (size_t)(k1 + krow) * HID + kq * 16];
            #pragma unroll
            for (int i = 0; i < 4; i++) kr[i] = *(const float4*)(kp + i * 4);
            #pragma unroll
            for (int i = 0; i < 4; i++) {
                int key = k1 + vk + i * 16;
                const float* vp = &V[base + (size_t)key * HID + vd];
                vr[4*i+0] = vp[0]; vr[4*i+1] = vp[HID];
                vr[4*i+2] = vp[2*HID]; vr[4*i+3] = vp[3*HID];
            }
            if (tid < 64)
                mreg = mask[(size_t)b * SEQ + k1 + tid];
        }

        // ---- compute tile t: fused S -> exp -> PV per 16-key group ----
        const uint32_t KsBuf = smB + (uint32_t)st * KS_BYTES;
        const uint32_t VtBuf = smB + 2 * KS_BYTES + (uint32_t)st * VT_BYTES;
        const float* md = madd + st * 64;

        #pragma unroll
        for (int p = 0; p < 4; p++) {
            float c0[4] = {0.f, 0.f, 0.f, 0.f};
            float c1[4] = {0.f, 0.f, 0.f, 0.f};
            const uint32_t kb = KsBuf + (uint32_t)p * (16 * BSTR) + boffB;
            #pragma unroll
            for (int k16 = 0; k16 < 4; k16++) {
                uint32_t kf[4];
                ldsm_x4(kf, kb + k16 * 32);
                mma_bf16(c0, Qb[k16], kf);
                mma_bf16(c1, Qb[k16], kf + 2);
            }
            const int colb0 = p * 16 + 2 * four;
            const int colb1 = colb0 + 8;
            const float ma0 = md[colb0], mb0 = md[colb0 + 1];
            const float ma1 = md[colb1], mb1 = md[colb1 + 1];
            float e00 = __expf(c0[0] * 0.125f + ma0);
            float e01 = __expf(c0[1] * 0.125f + mb0);
            float e02 = __expf(c0[2] * 0.125f + ma0);
            float e03 = __expf(c0[3] * 0.125f + mb0);
            float e10 = __expf(c1[0] * 0.125f + ma1);
            float e11 = __expf(c1[1] * 0.125f + mb1);
            float e12 = __expf(c1[2] * 0.125f + ma1);
            float e13 = __expf(c1[3] * 0.125f + mb1);
            rs0 += e00 + e01 + e10 + e11;
            rs1 += e02 + e03 + e12 + e13;
            // m16n8k8-C == m16n8k16-bf16-A after packing
            uint32_t a[4];
            a[0] = bfpack(e00, e01);
            a[1] = bfpack(e02, e03);
            a[2] = bfpack(e10, e11);
            a[3] = bfpack(e12, e13);

            const uint32_t vb = VtBuf + (uint32_t)p * 32 + boffB;
            #pragma unroll
            for (int jdp = 0; jdp < 4; jdp++) {
                uint32_t vf[4];
                ldsm_x4(vf, vb + jdp * (16 * BSTR));
                mma_bf16(ctx[2 * jdp],     a, vf);
                mma_bf16(ctx[2 * jdp + 1], a, vf + 2);
            }
        }

        // ---- complete stage t+1 (pack + store K/V, mask), fence ----
        if (more) {
            #pragma unroll
            for (int i = 0; i < 2; i++) {
                uint4 pk = make_uint4(bfpack(kr[2*i].x, kr[2*i].y),
                                      bfpack(kr[2*i].z, kr[2*i].w),
                                      bfpack(kr[2*i+1].x, kr[2*i+1].y),
                                      bfpack(kr[2*i+1].z, kr[2*i+1].w));
                *(uint4*)(smc + nst * KS_BYTES + krow * BSTR + kq * 32 + i * 16) = pk;
            }
            #pragma unroll
            for (int i = 0; i < 4; i++) {
                uint2 pk = make_uint2(bfpack(vr[4*i], vr[4*i+1]),
                                      bfpack(vr[4*i+2], vr[4*i+3]));
                *(uint2*)(smc + 2*KS_BYTES + nst * VT_BYTES
                              + vd * BSTR + (vk + i * 16) * 2) = pk;
            }
            if (tid < 64)
                madd[nst * 64 + tid] = (1.0f - mreg) * -10000.0f;
            __syncthreads();
        }
    }

    // ---- normalize and write ----
    rs0 += __shfl_xor_sync(0xffffffffu, rs0, 1);
    rs0 += __shfl_xor_sync(0xffffffffu, rs0, 2);
    rs1 += __shfl_xor_sync(0xffffffffu, rs1, 1);
    rs1 += __shfl_xor_sync(0xffffffffu, rs1, 2);
    const float inv0 = 1.0f / rs0, inv1 = 1.0f / rs1;

    const int r0 = q0 + m0 + grp, r1 = r0 + 8;
    #pragma unroll
    for (int jd = 0; jd < 8; jd++) {
        int col = jd * 8 + 2 * four;
        *(float2*)&O[base + (size_t)r0 * HID + col] =
            make_float2(ctx[jd][0] * inv0, ctx[jd][1] * inv0);
        *(float2*)&O[base + (size_t)r1 * HID + col] =
            make_float2(ctx[jd][2] * inv1, ctx[jd][3] * inv1);
    }
}

// ===========================================================================
// tf32 mma.sync projection GEMM (raw fp32 bits, no explicit cvt).
// CTA 128x128, k-chunk 32; 8 warps (2m x 4n), warp tile 64x32.
// ===========================================================================
#define GSTR 36
#define GRB  (GSTR * 4)   // 144

template <bool ADD_RESID>
__global__ __launch_bounds__(256)
void gemm_mma(const float* __restrict__ A, const float* __restrict__ W,
              const float* __restrict__ bias, const float* __restrict__ resid,
              float* __restrict__ C)
{
    __shared__ float As[128 * GSTR];   // [row][k]
    __shared__ float Ws[128 * GSTR];   // [n][k]  (W transposed)

    const int tid = threadIdx.x, wid = tid >> 5, lane = tid & 31;
    const int grp = lane >> 2, four = lane & 3;
    const int wm = wid & 1, wn = wid >> 1;
    const int m0 = wm * 64, n0 = wn * 32;
    const int bm = blockIdx.y * 128, bn = blockIdx.x * 128;
    const int lx7 = lane & 7;

    const uint32_t AsB = smem_u32(As), WsB = smem_u32(Ws);
    const uint32_t aoff = (uint32_t)(lx7 + ((lane & 8) ? 8 : 0)) * GRB
                        + ((lane & 16) ? 16u : 0u);
    const uint32_t boff = (uint32_t)(lx7 + ((lane & 16) >> 1)) * GRB
                        + ((lane & 8) ? 16u : 0u);

    float acc[4][4][4];
    #pragma unroll
    for (int mt = 0; mt < 4; mt++)
        #pragma unroll
        for (int nt = 0; nt < 4; nt++)
            #pragma unroll
            for (int i = 0; i < 4; i++) acc[mt][nt][i] = 0.f;

    for (int kc = 0; kc < HID / 32; kc++) {
        const int k0 = kc * 32;
        #pragma unroll
        for (int i = 0; i < 4; i++) {
            int s = tid + i * 256, r = s >> 3, c4 = s & 7;
            CP_ASYNC16(AsB + (uint32_t)(r * GSTR + c4 * 4) * 4,
                       &A[(size_t)(bm + r) * HID + k0 + c4 * 4]);
        }
        CP_COMMIT();
        #pragma unroll
        for (int i = 0; i < 4; i++) {
            int k4 = (tid >> 7) + i * 2;     // 0..7
            int n  = tid & 127;
            const float* wp = &W[(size_t)(k0 + k4 * 4) * HID + bn + n];
            float4 v;
            v.x = wp[0]; v.y = wp[HID]; v.z = wp[2 * HID]; v.w = wp[3 * HID];
            *(float4*)&Ws[n * GSTR + k4 * 4] = v;
        }
        CP_WAIT0();
        __syncthreads();

        #pragma unroll
        for (int ks = 0; ks < 4; ks++) {
            uint32_t af[4][4], bf[2][4];
            #pragma unroll
            for (int mt = 0; mt < 4; mt++)
                ldsm_x4(af[mt], AsB + (uint32_t)(m0 + mt * 16) * GRB + ks * 32 + aoff);
            #pragma unroll
            for (int np = 0; np < 2; np++)
                ldsm_x4(bf[np], WsB + (uint32_t)(n0 + np * 16) * GRB + ks * 32 + boff);
            #pragma unroll
            for (int mt = 0; mt < 4; mt++)
                #pragma unroll
                for (int nt = 0; nt < 4; nt++)
                    mma_tf32(acc[mt][nt], af[mt], &bf[nt >> 1][(nt & 1) * 2]);
        }
        __syncthreads();
    }

    #pragma unroll
    for (int mt = 0; mt < 4; mt++) {
        int r0 = bm + m0 + mt * 16 + grp, r1 = r0 + 8;
        #pragma unroll
        for (int nt = 0; nt < 4; nt++) {
            int col = bn + n0 + nt * 8 + 2 * four;
            float b0 = bias[col], b1 = bias[col + 1];
            float2 o0 = make_float2(acc[mt][nt][0] + b0, acc[mt][nt][1] + b1);
            float2 o1 = make_float2(acc[mt][nt][2] + b0, acc[mt][nt][3] + b1);
            if (ADD_RESID) {
                float2 h0 = *(const float2*)&resid[(size_t)r0 * HID + col];
                float2 h1 = *(const float2*)&resid[(size_t)r1 * HID + col];
                o0.x += h0.x; o0.y += h0.y; o1.x += h1.x; o1.y += h1.y;
            }
            *(float2*)&C[(size_t)r0 * HID + col] = o0;
            *(float2*)&C[(size_t)r1 * HID + col] = o1;
        }
    }
}

// ---------------------------------------------------------------------------
// LayerNorm
// ---------------------------------------------------------------------------
__global__ __launch_bounds__(256)
void ln_kernel(float* __restrict__ X, const float* __restrict__ gamma,
               const float* __restrict__ beta)
{
    __shared__ float ss[8], ss2[8];
    const int row = blockIdx.x;
    float* x = X + (size_t)row * HID;
    const int tid = threadIdx.x;

    float v[3], s = 0.f, s2 = 0.f;
    #pragma unroll
    for (int i = 0; i < 3; i++) {
        v[i] = x[tid + i * 256];
        s += v[i]; s2 += v[i] * v[i];
    }
    #pragma unroll
    for (int off = 16; off; off >>= 1) {
        s  += __shfl_xor_sync(0xffffffffu, s,  off);
        s2 += __shfl_xor_sync(0xffffffffu, s2, off);
    }
    if ((tid & 31) == 0) { ss[tid >> 5] = s; ss2[tid >> 5] = s2; }
    __syncthreads();
    s = 0.f; s2 = 0.f;
    #pragma unroll
    for (int i = 0; i < 8; i++) { s += ss[i]; s2 += ss2[i]; }

    const float mu  = s * (1.0f / HID);
    const float var = s2 * (1.0f / HID) - mu * mu;
    const float inv = rsqrtf(var + 1e-5f);
    #pragma unroll
    for (int i = 0; i < 3; i++) {
        int c = tid + i * 256;
        x[c] = (v[i] - mu) * inv * gamma[c] + beta[c];
    }
}

// ---------------------------------------------------------------------------
// Launch
// ---------------------------------------------------------------------------
extern "C" void kernel_launch(void* const* d_in, const int* in_sizes, int n_in,
                              void* d_out, int out_size)
{
    (void)in_sizes; (void)n_in; (void)out_size;
    const float* hidden = (const float*)d_in[0];
    const float* mask   = (const float*)d_in[1];
    const float* Wq = (const float*)d_in[2];
    const float* bq = (const float*)d_in[3];
    const float* Wk = (const float*)d_in[4];
    const float* bk = (const float*)d_in[5];
    const float* Wv = (const float*)d_in[6];
    const float* bv = (const float*)d_in[7];
    const float* Wo = (const float*)d_in[8];
    const float* bo = (const float*)d_in[9];
    const float* gamma = (const float*)d_in[10];
    const float* beta  = (const float*)d_in[11];
    float* out = (float*)d_out;

    float *q, *k, *v, *ctx;
    cudaGetSymbolAddress((void**)&q,   g_q);
    cudaGetSymbolAddress((void**)&k,   g_k);
    cudaGetSymbolAddress((void**)&v,   g_v);
    cudaGetSymbolAddress((void**)&ctx, g_ctx);

    const dim3 gg(HID / 128, NROWS / 128);   // (6, 64)

    gemm_mma<false><<<gg, 256>>>(hidden, Wq, bq, nullptr, q);
    gemm_mma<false><<<gg, 256>>>(hidden, Wk, bk, nullptr, k);
    gemm_mma<false><<<gg, 256>>>(hidden, Wv, bv, nullptr, v);

    cudaFuncSetAttribute(attn_mma, cudaFuncAttributeMaxDynamicSharedMemorySize,
                         ATTN_SMEM);
    attn_mma<<<dim3(SEQ / 128, NH, BATCH), 256, ATTN_SMEM>>>(q, k, v, mask, ctx);

    gemm_mma<true><<<gg, 256>>>(ctx, Wo, bo, hidden, out);
    ln_kernel<<<NROWS, 256>>>(out, gamma, beta);
}